// round 16
// baseline (speedup 1.0000x reference)
#include <cuda_runtime.h>
#include <cuda_fp16.h>
#include <cuda_bf16.h>
#include <cstddef>
#include <cstdint>

// ---------------------------------------------------------------------------
// GCN: 5 GraphConv + 3 edge-weighted aggregations. CSR-gather + tensor cores.
// R16 = R15 (241.6us) with ONE mechanism change: deg_k and fill_k batched to
// 4 edges/thread via int4/float4 loads -> 4 independent atomic chains in
// flight (they were MLP=1 ATOMG-latency-bound: fill_k issue=5.1%, 15.2us).
// Hot path + scan byte-frozen from R15.
// ---------------------------------------------------------------------------

#define NN 50000
#define NE 800000
#define NB_SCAN ((NN + 255) / 256)

__device__ int   g_cnt3[3 * NN];           // [ideg | odeg | fill-cursor]
__device__ int   g_off[NN + 1];
__device__ int   g_bsum[256];
__device__ __align__(16) int2  g_edge[NE]; // {src, __float_as_int(efet)}
__device__ float g_norm_out[NN];
__device__ float g_norm_in[NN];
__device__ __align__(16) float g_bufA[(size_t)NN * 256];
__device__ __align__(16) float g_bufB[(size_t)NN * 256];
__device__ __align__(16) float g_bufC[(size_t)NN * 256];
// transposed fp16 weights: W2t[128][256], W3t[64][128], W4t[32][64]
__device__ __align__(16) __half g_w2t[128 * 256];
__device__ __align__(16) __half g_w3t[64 * 128];
__device__ __align__(16) __half g_w4t[32 * 64];

// ---- degrees: 4 edges per thread, 8 independent atomics in flight ----------

__global__ void deg_k(const int* __restrict__ src, const int* __restrict__ dst) {
    int i = blockIdx.x * blockDim.x + threadIdx.x;     // i < NE/4
    if (i >= NE / 4) return;
    int4 s = ((const int4*)src)[i];
    int4 d = ((const int4*)dst)[i];
    atomicAdd(&g_cnt3[NN + s.x], 1);
    atomicAdd(&g_cnt3[NN + s.y], 1);
    atomicAdd(&g_cnt3[NN + s.z], 1);
    atomicAdd(&g_cnt3[NN + s.w], 1);
    atomicAdd(&g_cnt3[d.x], 1);
    atomicAdd(&g_cnt3[d.y], 1);
    atomicAdd(&g_cnt3[d.z], 1);
    atomicAdd(&g_cnt3[d.w], 1);
}

// ---- multi-block scan phase 1 + norms (coalesced, parallel) ----------------

__global__ void bscan_k() {
    __shared__ int sh[256];
    int t = threadIdx.x;
    int i = blockIdx.x * 256 + t;
    int id = (i < NN) ? g_cnt3[i] : 0;
    sh[t] = id;
    __syncthreads();
    for (int o = 1; o < 256; o <<= 1) {
        int u = (t >= o) ? sh[t - o] : 0;
        __syncthreads();
        sh[t] += u;
        __syncthreads();
    }
    if (i < NN) {
        g_off[i] = sh[t] - id;                 // local exclusive
        g_norm_in[i]  = rsqrtf(fmaxf((float)id, 1.0f));
        g_norm_out[i] = rsqrtf(fmaxf((float)g_cnt3[NN + i], 1.0f));
    }
    if (t == 255) g_bsum[blockIdx.x] = sh[255];
}

// ---- phase 2: each block redundantly scans the block sums, adds its offset -

__global__ void badd_k() {
    __shared__ int sh[256];
    int t = threadIdx.x;
    sh[t] = (t < NB_SCAN) ? g_bsum[t] : 0;
    __syncthreads();
    for (int o = 1; o < 256; o <<= 1) {
        int u = (t >= o) ? sh[t - o] : 0;
        __syncthreads();
        sh[t] += u;
        __syncthreads();
    }
    int boff = (blockIdx.x == 0) ? 0 : sh[blockIdx.x - 1];
    int i = blockIdx.x * 256 + t;
    if (i < NN) g_off[i] += boff;
    if (blockIdx.x == 0 && t == 0) g_off[NN] = NE;
}

// ---- CSR fill: 4 edges per thread, 4 independent atomic chains -------------

__global__ void fill_k(const int* __restrict__ src, const int* __restrict__ dst,
                       const float* __restrict__ efet) {
    int i = blockIdx.x * blockDim.x + threadIdx.x;     // i < NE/4
    if (i >= NE / 4) return;
    int4 s = ((const int4*)src)[i];
    int4 d = ((const int4*)dst)[i];
    float4 f = ((const float4*)efet)[i];
    int p0 = g_off[d.x] + atomicAdd(&g_cnt3[2 * NN + d.x], 1);
    int p1 = g_off[d.y] + atomicAdd(&g_cnt3[2 * NN + d.y], 1);
    int p2 = g_off[d.z] + atomicAdd(&g_cnt3[2 * NN + d.z], 1);
    int p3 = g_off[d.w] + atomicAdd(&g_cnt3[2 * NN + d.w], 1);
    g_edge[p0] = make_int2(s.x, __float_as_int(f.x));
    g_edge[p1] = make_int2(s.y, __float_as_int(f.y));
    g_edge[p2] = make_int2(s.z, __float_as_int(f.z));
    g_edge[p3] = make_int2(s.w, __float_as_int(f.w));
}

// ---- all W -> Wt fp16 transposes in one kernel -----------------------------

__global__ void wcvt_all_k(const float* __restrict__ W2,
                           const float* __restrict__ W3,
                           const float* __restrict__ W4) {
    int i = blockIdx.x * blockDim.x + threadIdx.x;
    if (i < 256 * 128) {
        int k = i / 128, n = i % 128;
        g_w2t[(size_t)n * 256 + k] = __float2half(W2[i]);
    } else if (i < 256 * 128 + 128 * 64) {
        int j = i - 256 * 128;
        int k = j / 64, n = j % 64;
        g_w3t[(size_t)n * 128 + k] = __float2half(W3[j]);
    } else if (i < 256 * 128 + 128 * 64 + 64 * 32) {
        int j = i - 256 * 128 - 128 * 64;
        int k = j / 32, n = j % 32;
        g_w4t[(size_t)n * 64 + k] = __float2half(W4[j]);
    }
}

// ---- fp32 gather (final 4-wide) --------------------------------------------
// WMODE: 0 = w=1, 1 = w=efet, 2 = w=out_norm[src]

template <int F, int WMODE, bool EPI, bool RELU>
__global__ void gather_k(const float* __restrict__ m,
                         const float* __restrict__ b,
                         float* __restrict__ out) {
    constexpr int NT = F / 4;
    constexpr int NPB = 256 / NT;
    int t = threadIdx.x;
    int node = blockIdx.x * NPB + t / NT;
    int c = t % NT;
    if (node >= NN) return;
    int beg = g_off[node], end = g_off[node + 1];

    float4 acc = make_float4(0.f, 0.f, 0.f, 0.f);
    for (int e = beg; e < end; e++) {
        int2 sc = g_edge[e];
        int s = sc.x;
        float w = 1.0f;
        if (WMODE == 1) w = __int_as_float(sc.y);
        if (WMODE == 2) w = g_norm_out[s];
        float4 v = *(const float4*)(m + (size_t)s * F + c * 4);
        acc.x += v.x * w; acc.y += v.y * w; acc.z += v.z * w; acc.w += v.w * w;
    }
    if (EPI) {
        float ni = g_norm_in[node];
        acc.x = acc.x * ni + b[c * 4 + 0];
        acc.y = acc.y * ni + b[c * 4 + 1];
        acc.z = acc.z * ni + b[c * 4 + 2];
        acc.w = acc.w * ni + b[c * 4 + 3];
    }
    if (RELU) {
        acc.x = fmaxf(acc.x, 0.f); acc.y = fmaxf(acc.y, 0.f);
        acc.z = fmaxf(acc.z, 0.f); acc.w = fmaxf(acc.w, 0.f);
    }
    *(float4*)(out + (size_t)node * F + c * 4) = acc;
}

// ---- fp16-input gather ------------------------------------------------------
// 8 halves per thread, fp32 accumulation, x2 edge unroll (frozen config).
// ONORM: multiply final result by out_norm[node].  OH: fp16 output.

__device__ __forceinline__ void acc8(float* a, uint4 r, float w) {
    float2 f;
    f = __half22float2(*(const __half2*)&r.x); a[0] += f.x * w; a[1] += f.y * w;
    f = __half22float2(*(const __half2*)&r.y); a[2] += f.x * w; a[3] += f.y * w;
    f = __half22float2(*(const __half2*)&r.z); a[4] += f.x * w; a[5] += f.y * w;
    f = __half22float2(*(const __half2*)&r.w); a[6] += f.x * w; a[7] += f.y * w;
}

template <int F, int WMODE, bool EPI, bool RELU, bool ONORM, bool OH>
__global__ void gather_h_k(const __half* __restrict__ m,
                           const float* __restrict__ b,
                           void* __restrict__ outp) {
    constexpr int NT = F / 8;
    constexpr int NPB = 256 / NT;
    int t = threadIdx.x;
    int node = blockIdx.x * NPB + t / NT;
    int c = t % NT;
    if (node >= NN) return;
    int beg = g_off[node], end = g_off[node + 1];

    float acc[8];
#pragma unroll
    for (int i = 0; i < 8; i++) acc[i] = 0.f;

    const uint4* base = (const uint4*)m;
    int e = beg;
    for (; e + 2 <= end; e += 2) {
        int2 sc0 = g_edge[e], sc1 = g_edge[e + 1];
        float w0 = 1.f, w1 = 1.f;
        if (WMODE == 1) { w0 = __int_as_float(sc0.y); w1 = __int_as_float(sc1.y); }
        uint4 r0 = base[(size_t)sc0.x * NT + c];
        uint4 r1 = base[(size_t)sc1.x * NT + c];
        acc8(acc, r0, w0);
        acc8(acc, r1, w1);
    }
    if (e < end) {
        int2 sc = g_edge[e];
        float w = (WMODE == 1) ? __int_as_float(sc.y) : 1.f;
        uint4 r = base[(size_t)sc.x * NT + c];
        acc8(acc, r, w);
    }

    if (EPI) {
        float ni = g_norm_in[node];
#pragma unroll
        for (int i = 0; i < 8; i++) acc[i] = acc[i] * ni + b[c * 8 + i];
    }
    if (RELU) {
#pragma unroll
        for (int i = 0; i < 8; i++) acc[i] = fmaxf(acc[i], 0.f);
    }
    if (ONORM) {
        float no = g_norm_out[node];
#pragma unroll
        for (int i = 0; i < 8; i++) acc[i] *= no;
    }
    if (OH) {
        __half2 h0 = __floats2half2_rn(acc[0], acc[1]);
        __half2 h1 = __floats2half2_rn(acc[2], acc[3]);
        __half2 h2 = __floats2half2_rn(acc[4], acc[5]);
        __half2 h3 = __floats2half2_rn(acc[6], acc[7]);
        uint4 r;
        r.x = *(const unsigned*)&h0; r.y = *(const unsigned*)&h1;
        r.z = *(const unsigned*)&h2; r.w = *(const unsigned*)&h3;
        ((uint4*)outp)[(size_t)node * NT + c] = r;
    } else {
        float* o = (float*)outp + (size_t)node * F + c * 8;
        *(float4*)(o + 0) = make_float4(acc[0], acc[1], acc[2], acc[3]);
        *(float4*)(o + 4) = make_float4(acc[4], acc[5], acc[6], acc[7]);
    }
}

// ---- tensor-core GEMM: D[M,N] = A[M,K] @ W[K,N], fp16 in / fp32 acc --------

template <int K, int N>
__global__ void mma_gemm_k(const __half* __restrict__ A,
                           const __half* __restrict__ Wt,
                           __half* __restrict__ D) {
    constexpr int WN = (N >= 64) ? 64 : N;       // warp n-extent
    constexpr int TN = WN / 8;                   // n8 tiles per warp
    constexpr int WARPS_N = N / WN;
    constexpr int WARPS_M = 8 / WARPS_N;
    constexpr int BM = WARPS_M * 16;
    constexpr int PITCH = K + 8;                 // +16B pad -> bank rotation
    constexpr int KC = K / 16;                   // k16 chunks

    __shared__ __half sA[BM * PITCH];

    const int tid = threadIdx.x;
    const int lane = tid & 31;
    const int wid = tid >> 5;
    const int wm = wid % WARPS_M;
    const int wn = wid / WARPS_M;
    const int blockStart = blockIdx.x * BM;

    for (int i = tid; i < BM * (K / 8); i += 256) {
        int row = i / (K / 8), chunk = i % (K / 8);
        int node = blockStart + row;
        uint4 v = make_uint4(0, 0, 0, 0);
        if (node < NN) v = ((const uint4*)A)[(size_t)node * (K / 8) + chunk];
        *(uint4*)(&sA[row * PITCH + chunk * 8]) = v;
    }
    __syncthreads();

    float acc[TN][4];
#pragma unroll
    for (int t = 0; t < TN; t++)
#pragma unroll
        for (int i = 0; i < 4; i++) acc[t][i] = 0.f;

    const int q = lane >> 3, r = lane & 7;
    const int arow = wm * 16 + r + 8 * (q & 1);
    const int acol0 = 8 * (q >> 1);
    unsigned abase;
    {
        const void* p = &sA[arow * PITCH + acol0];
        asm("{ .reg .u64 t; cvta.to.shared.u64 t, %1; cvt.u32.u64 %0, t; }"
            : "=r"(abase) : "l"(p));
    }

    const __half* wbase = Wt + (size_t)(wn * WN + (lane >> 2)) * K + (lane & 3) * 2;

#pragma unroll
    for (int kc = 0; kc < KC; kc++) {
        unsigned a0, a1, a2, a3;
        asm volatile("ldmatrix.sync.aligned.m8n8.x4.shared.b16 {%0,%1,%2,%3}, [%4];"
                     : "=r"(a0), "=r"(a1), "=r"(a2), "=r"(a3)
                     : "r"(abase + kc * 32));
#pragma unroll
        for (int tn = 0; tn < TN; tn++) {
            unsigned b0 = *(const unsigned*)(wbase + (size_t)tn * 8 * K + kc * 16);
            unsigned b1 = *(const unsigned*)(wbase + (size_t)tn * 8 * K + kc * 16 + 8);
            asm volatile(
                "mma.sync.aligned.m16n8k16.row.col.f32.f16.f16.f32 "
                "{%0,%1,%2,%3}, {%4,%5,%6,%7}, {%8,%9}, {%0,%1,%2,%3};"
                : "+f"(acc[tn][0]), "+f"(acc[tn][1]), "+f"(acc[tn][2]), "+f"(acc[tn][3])
                : "r"(a0), "r"(a1), "r"(a2), "r"(a3), "r"(b0), "r"(b1));
        }
    }

    const int node0 = blockStart + wm * 16 + (lane >> 2);
    const int node1 = node0 + 8;
#pragma unroll
    for (int tn = 0; tn < TN; tn++) {
        int gcol = wn * WN + tn * 8 + (lane & 3) * 2;
        if (node0 < NN) {
            __half2 h = __floats2half2_rn(acc[tn][0], acc[tn][1]);
            *(unsigned*)(D + (size_t)node0 * N + gcol) = *(const unsigned*)&h;
        }
        if (node1 < NN) {
            __half2 h = __floats2half2_rn(acc[tn][2], acc[tn][3]);
            *(unsigned*)(D + (size_t)node1 * N + gcol) = *(const unsigned*)&h;
        }
    }
}

// ---- fused gc1: gather 16-wide scaled x + (agg @ W1)*in_norm+b1, relu ------

__global__ void g1_k(const float* __restrict__ x, const float* __restrict__ W1,
                     const float* __restrict__ b1, __half* __restrict__ out) {
    __shared__ float sX[64 * 16];
    const int tid = threadIdx.x;
    const int nbase = blockIdx.x * 64;

    {
        int g = tid / 4, c = tid % 4;
        int node = nbase + g;
        float4 a = make_float4(0.f, 0.f, 0.f, 0.f);
        if (node < NN) {
            int beg = g_off[node], end = g_off[node + 1];
            for (int e = beg; e < end; e++) {
                int s = g_edge[e].x;
                float w = g_norm_out[s];
                float4 v = *(const float4*)(x + (size_t)s * 16 + c * 4);
                a.x += v.x * w; a.y += v.y * w; a.z += v.z * w; a.w += v.w * w;
            }
        }
        *(float4*)(&sX[g * 16 + c * 4]) = a;
    }
    __syncthreads();

    const int j = tid;
    float w[16];
#pragma unroll
    for (int k = 0; k < 16; k++) w[k] = W1[k * 256 + j];
    float bj = b1[j];
#pragma unroll 4
    for (int ln = 0; ln < 64; ln++) {
        int node = nbase + ln;
        if (node >= NN) break;
        float acc = 0.f;
#pragma unroll
        for (int k = 0; k < 16; k++) acc += sX[ln * 16 + k] * w[k];
        acc = acc * g_norm_in[node] + bj;
        out[(size_t)node * 256 + j] = __float2half(fmaxf(acc, 0.f));
    }
}

// ---- fused gc4-agg + gemm5: h4 = relu(agg(m4)*ni+b4); m5 = (h4*no)@W5 ------

__global__ void g45_k(const __half* __restrict__ m4, const float* __restrict__ b4,
                      const float* __restrict__ W5, float* __restrict__ m5) {
    __shared__ float sH[64 * 32];
    __shared__ float sW[32 * 4];
    const int tid = threadIdx.x;
    if (tid < 128) sW[tid] = W5[tid];
    const int g = tid / 4, c = tid % 4;     // 64 nodes x 4 threads
    const int node = blockIdx.x * 64 + g;

    float acc[8];
#pragma unroll
    for (int i = 0; i < 8; i++) acc[i] = 0.f;
    if (node < NN) {
        int beg = g_off[node], end = g_off[node + 1];
        const uint4* base = (const uint4*)m4;     // row stride = 4 uint4s
        int e = beg;
        for (; e + 2 <= end; e += 2) {
            int2 sc0 = g_edge[e], sc1 = g_edge[e + 1];
            uint4 r0 = base[(size_t)sc0.x * 4 + c];
            uint4 r1 = base[(size_t)sc1.x * 4 + c];
            acc8(acc, r0, 1.f);
            acc8(acc, r1, 1.f);
        }
        if (e < end) {
            int2 sc = g_edge[e];
            uint4 r = base[(size_t)sc.x * 4 + c];
            acc8(acc, r, 1.f);
        }
        float ni = g_norm_in[node];
        float no = g_norm_out[node];
#pragma unroll
        for (int i = 0; i < 8; i++)
            acc[i] = fmaxf(acc[i] * ni + b4[c * 8 + i], 0.f) * no;
    }
#pragma unroll
    for (int i = 0; i < 8; i++) sH[g * 32 + c * 8 + i] = acc[i];
    __syncthreads();

    if (node >= NN) return;
    float o = 0.f;
#pragma unroll
    for (int k = 0; k < 32; k++) o += sH[g * 32 + k] * sW[k * 4 + c];
    m5[(size_t)node * 4 + c] = o;
}

// ---------------------------------------------------------------------------

static inline int cdiv(long long a, int b) { return (int)((a + b - 1) / b); }

extern "C" void kernel_launch(void* const* d_in, const int* in_sizes, int n_in,
                              void* d_out, int out_size) {
    (void)in_sizes; (void)n_in; (void)out_size;
    const float* x    = (const float*)d_in[0];
    const float* efet = (const float*)d_in[1];
    const int*   src  = (const int*)d_in[2];
    const int*   dst  = (const int*)d_in[3];
    const float* W1 = (const float*)d_in[4];  const float* b1 = (const float*)d_in[5];
    const float* W2 = (const float*)d_in[6];  const float* b2 = (const float*)d_in[7];
    const float* W3 = (const float*)d_in[8];  const float* b3 = (const float*)d_in[9];
    const float* W4 = (const float*)d_in[10]; const float* b4 = (const float*)d_in[11];
    const float* W5 = (const float*)d_in[12]; const float* b5 = (const float*)d_in[13];
    float* out = (float*)d_out;

    float *bufA, *bufB, *bufC;
    int *cnt3;
    __half *w2t, *w3t, *w4t;
    cudaGetSymbolAddress((void**)&bufA, g_bufA);
    cudaGetSymbolAddress((void**)&bufB, g_bufB);
    cudaGetSymbolAddress((void**)&bufC, g_bufC);
    cudaGetSymbolAddress((void**)&cnt3, g_cnt3);
    cudaGetSymbolAddress((void**)&w2t, g_w2t);
    cudaGetSymbolAddress((void**)&w3t, g_w3t);
    cudaGetSymbolAddress((void**)&w4t, g_w4t);
    __half* hA = (__half*)bufA;
    __half* hB = (__half*)bufB;
    __half* hC = (__half*)bufC;

    const int TB = 256;

    // ---- preprocessing (R15 structure; edge kernels 4-wide batched)
    cudaMemsetAsync(cnt3, 0, 3 * NN * sizeof(int));
    deg_k<<<cdiv(NE / 4, TB), TB>>>(src, dst);
    bscan_k<<<NB_SCAN, 256>>>();
    badd_k<<<NB_SCAN, 256>>>();
    fill_k<<<cdiv(NE / 4, TB), TB>>>(src, dst, efet);
    wcvt_all_k<<<cdiv(256 * 128 + 128 * 64 + 64 * 32, TB), TB>>>(W2, W3, W4);

    // ---- gc1 fused: g1 = relu((agg16(x*no) @ W1)*ni + b1) -> fp16
    g1_k<<<cdiv(NN, 64), TB>>>(x, W1, b1, hB);                                // g1: hB

    // ---- y1 = g1 @ W2 (mma 256->128) BEFORE ewa1 (commuted)
    mma_gemm_k<256, 128><<<cdiv(NN, 64), TB>>>(hB, w2t, hA);                  // y1: hA
    // ---- ewa1 at width 128: m2 = ewa(y1) * out_norm (relu is identity)
    gather_h_k<128, 1, false, false, true, true><<<cdiv(NN, 16), TB>>>(hA, nullptr, hC);
    // ---- gc2 aggregation: g2 = relu(agg(m2)*ni + b2)
    gather_h_k<128, 0, true, true, false, true><<<cdiv(NN, 16), TB>>>(hC, b2, hB); // g2: hB

    // ---- y2 = g2 @ W3 (mma 128->64) BEFORE ewa2
    mma_gemm_k<128, 64><<<cdiv(NN, 128), TB>>>(hB, w3t, hA);                  // y2: hA
    // ---- ewa2 at width 64
    gather_h_k<64, 1, false, false, true, true><<<cdiv(NN, 32), TB>>>(hA, nullptr, hC);
    // ---- gc3 aggregation: g3 = relu(agg(m3)*ni + b3)
    gather_h_k<64, 0, true, true, false, true><<<cdiv(NN, 32), TB>>>(hC, b3, hB);  // g3: hB

    // ---- y3 = g3 @ W4 (mma 64->32) BEFORE ewa3
    mma_gemm_k<64, 32><<<cdiv(NN, 128), TB>>>(hB, w4t, hA);                   // y3: hA
    // ---- ewa3 at width 32
    gather_h_k<32, 1, false, false, true, true><<<cdiv(NN, 64), TB>>>(hA, nullptr, hC);

    // ---- gc4-agg + gemm5 fused: m5 = (relu(agg(m4)*ni+b4)*no) @ W5
    g45_k<<<cdiv(NN, 64), TB>>>(hC, b4, W5, bufB);                            // m5: bufB

    // ---- gc5 aggregation: out = agg(m5)*ni + b5
    gather_k<4, 0, true, false><<<cdiv(NN, 256), TB>>>(bufB, b5, out);
}

// round 17
// speedup vs baseline: 1.0050x; 1.0050x over previous
#include <cuda_runtime.h>
#include <cuda_fp16.h>
#include <cuda_bf16.h>
#include <cstddef>
#include <cstdint>

// ---------------------------------------------------------------------------
// GCN: 5 GraphConv + 3 edge-weighted aggregations. CSR-gather + tensor cores.
// R17 = R15 (241.6us; R16's atomic batching reverted — it was neutral-negative
// with occupancy loss) + ONE hot-path change: gather_h_k edge loop unrolled
// x4 (4 independent row loads in flight per thread; thread mapping unchanged).
// Regime probe: latency-bound gathers -> ~225us; L2-BW-bound -> ~241us.
// ---------------------------------------------------------------------------

#define NN 50000
#define NE 800000
#define NB_SCAN ((NN + 255) / 256)

__device__ int   g_cnt3[3 * NN];           // [ideg | odeg | fill-cursor]
__device__ int   g_off[NN + 1];
__device__ int   g_bsum[256];
__device__ __align__(16) int2  g_edge[NE]; // {src, __float_as_int(efet)}
__device__ float g_norm_out[NN];
__device__ float g_norm_in[NN];
__device__ __align__(16) float g_bufA[(size_t)NN * 256];
__device__ __align__(16) float g_bufB[(size_t)NN * 256];
__device__ __align__(16) float g_bufC[(size_t)NN * 256];
// transposed fp16 weights: W2t[128][256], W3t[64][128], W4t[32][64]
__device__ __align__(16) __half g_w2t[128 * 256];
__device__ __align__(16) __half g_w3t[64 * 128];
__device__ __align__(16) __half g_w4t[32 * 64];

// ---- degrees (R15 scalar form) ----------------------------------------------

__global__ void deg_k(const int* __restrict__ src, const int* __restrict__ dst) {
    int e = blockIdx.x * blockDim.x + threadIdx.x;
    if (e < NE) {
        atomicAdd(&g_cnt3[NN + src[e]], 1);   // odeg
        atomicAdd(&g_cnt3[dst[e]], 1);        // ideg
    }
}

// ---- multi-block scan phase 1 + norms (coalesced, parallel) ----------------

__global__ void bscan_k() {
    __shared__ int sh[256];
    int t = threadIdx.x;
    int i = blockIdx.x * 256 + t;
    int id = (i < NN) ? g_cnt3[i] : 0;
    sh[t] = id;
    __syncthreads();
    for (int o = 1; o < 256; o <<= 1) {
        int u = (t >= o) ? sh[t - o] : 0;
        __syncthreads();
        sh[t] += u;
        __syncthreads();
    }
    if (i < NN) {
        g_off[i] = sh[t] - id;                 // local exclusive
        g_norm_in[i]  = rsqrtf(fmaxf((float)id, 1.0f));
        g_norm_out[i] = rsqrtf(fmaxf((float)g_cnt3[NN + i], 1.0f));
    }
    if (t == 255) g_bsum[blockIdx.x] = sh[255];
}

// ---- phase 2: each block redundantly scans the block sums, adds its offset -

__global__ void badd_k() {
    __shared__ int sh[256];
    int t = threadIdx.x;
    sh[t] = (t < NB_SCAN) ? g_bsum[t] : 0;
    __syncthreads();
    for (int o = 1; o < 256; o <<= 1) {
        int u = (t >= o) ? sh[t - o] : 0;
        __syncthreads();
        sh[t] += u;
        __syncthreads();
    }
    int boff = (blockIdx.x == 0) ? 0 : sh[blockIdx.x - 1];
    int i = blockIdx.x * 256 + t;
    if (i < NN) g_off[i] += boff;
    if (blockIdx.x == 0 && t == 0) g_off[NN] = NE;
}

// ---- CSR fill (R15 scalar form) ---------------------------------------------

__global__ void fill_k(const int* __restrict__ src, const int* __restrict__ dst,
                       const float* __restrict__ efet) {
    int e = blockIdx.x * blockDim.x + threadIdx.x;
    if (e < NE) {
        int d = dst[e];
        int pos = g_off[d] + atomicAdd(&g_cnt3[2 * NN + d], 1);
        g_edge[pos] = make_int2(src[e], __float_as_int(efet[e]));
    }
}

// ---- all W -> Wt fp16 transposes in one kernel -----------------------------

__global__ void wcvt_all_k(const float* __restrict__ W2,
                           const float* __restrict__ W3,
                           const float* __restrict__ W4) {
    int i = blockIdx.x * blockDim.x + threadIdx.x;
    if (i < 256 * 128) {
        int k = i / 128, n = i % 128;
        g_w2t[(size_t)n * 256 + k] = __float2half(W2[i]);
    } else if (i < 256 * 128 + 128 * 64) {
        int j = i - 256 * 128;
        int k = j / 64, n = j % 64;
        g_w3t[(size_t)n * 128 + k] = __float2half(W3[j]);
    } else if (i < 256 * 128 + 128 * 64 + 64 * 32) {
        int j = i - 256 * 128 - 128 * 64;
        int k = j / 32, n = j % 32;
        g_w4t[(size_t)n * 64 + k] = __float2half(W4[j]);
    }
}

// ---- fp32 gather (final 4-wide) --------------------------------------------
// WMODE: 0 = w=1, 1 = w=efet, 2 = w=out_norm[src]

template <int F, int WMODE, bool EPI, bool RELU>
__global__ void gather_k(const float* __restrict__ m,
                         const float* __restrict__ b,
                         float* __restrict__ out) {
    constexpr int NT = F / 4;
    constexpr int NPB = 256 / NT;
    int t = threadIdx.x;
    int node = blockIdx.x * NPB + t / NT;
    int c = t % NT;
    if (node >= NN) return;
    int beg = g_off[node], end = g_off[node + 1];

    float4 acc = make_float4(0.f, 0.f, 0.f, 0.f);
    for (int e = beg; e < end; e++) {
        int2 sc = g_edge[e];
        int s = sc.x;
        float w = 1.0f;
        if (WMODE == 1) w = __int_as_float(sc.y);
        if (WMODE == 2) w = g_norm_out[s];
        float4 v = *(const float4*)(m + (size_t)s * F + c * 4);
        acc.x += v.x * w; acc.y += v.y * w; acc.z += v.z * w; acc.w += v.w * w;
    }
    if (EPI) {
        float ni = g_norm_in[node];
        acc.x = acc.x * ni + b[c * 4 + 0];
        acc.y = acc.y * ni + b[c * 4 + 1];
        acc.z = acc.z * ni + b[c * 4 + 2];
        acc.w = acc.w * ni + b[c * 4 + 3];
    }
    if (RELU) {
        acc.x = fmaxf(acc.x, 0.f); acc.y = fmaxf(acc.y, 0.f);
        acc.z = fmaxf(acc.z, 0.f); acc.w = fmaxf(acc.w, 0.f);
    }
    *(float4*)(out + (size_t)node * F + c * 4) = acc;
}

// ---- fp16-input gather ------------------------------------------------------
// 8 halves per thread, fp32 accumulation, x4 edge unroll (R17 change: 4
// independent row loads in flight per thread).
// ONORM: multiply final result by out_norm[node].  OH: fp16 output.

__device__ __forceinline__ void acc8(float* a, uint4 r, float w) {
    float2 f;
    f = __half22float2(*(const __half2*)&r.x); a[0] += f.x * w; a[1] += f.y * w;
    f = __half22float2(*(const __half2*)&r.y); a[2] += f.x * w; a[3] += f.y * w;
    f = __half22float2(*(const __half2*)&r.z); a[4] += f.x * w; a[5] += f.y * w;
    f = __half22float2(*(const __half2*)&r.w); a[6] += f.x * w; a[7] += f.y * w;
}

template <int F, int WMODE, bool EPI, bool RELU, bool ONORM, bool OH>
__global__ void gather_h_k(const __half* __restrict__ m,
                           const float* __restrict__ b,
                           void* __restrict__ outp) {
    constexpr int NT = F / 8;
    constexpr int NPB = 256 / NT;
    int t = threadIdx.x;
    int node = blockIdx.x * NPB + t / NT;
    int c = t % NT;
    if (node >= NN) return;
    int beg = g_off[node], end = g_off[node + 1];

    float acc[8];
#pragma unroll
    for (int i = 0; i < 8; i++) acc[i] = 0.f;

    const uint4* base = (const uint4*)m;
    int e = beg;
    for (; e + 4 <= end; e += 4) {
        int2 sc0 = g_edge[e + 0], sc1 = g_edge[e + 1];
        int2 sc2 = g_edge[e + 2], sc3 = g_edge[e + 3];
        float w0 = 1.f, w1 = 1.f, w2 = 1.f, w3 = 1.f;
        if (WMODE == 1) {
            w0 = __int_as_float(sc0.y); w1 = __int_as_float(sc1.y);
            w2 = __int_as_float(sc2.y); w3 = __int_as_float(sc3.y);
        }
        uint4 r0 = base[(size_t)sc0.x * NT + c];
        uint4 r1 = base[(size_t)sc1.x * NT + c];
        uint4 r2 = base[(size_t)sc2.x * NT + c];
        uint4 r3 = base[(size_t)sc3.x * NT + c];
        acc8(acc, r0, w0);
        acc8(acc, r1, w1);
        acc8(acc, r2, w2);
        acc8(acc, r3, w3);
    }
    for (; e < end; e++) {
        int2 sc = g_edge[e];
        float w = (WMODE == 1) ? __int_as_float(sc.y) : 1.f;
        uint4 r = base[(size_t)sc.x * NT + c];
        acc8(acc, r, w);
    }

    if (EPI) {
        float ni = g_norm_in[node];
#pragma unroll
        for (int i = 0; i < 8; i++) acc[i] = acc[i] * ni + b[c * 8 + i];
    }
    if (RELU) {
#pragma unroll
        for (int i = 0; i < 8; i++) acc[i] = fmaxf(acc[i], 0.f);
    }
    if (ONORM) {
        float no = g_norm_out[node];
#pragma unroll
        for (int i = 0; i < 8; i++) acc[i] *= no;
    }
    if (OH) {
        __half2 h0 = __floats2half2_rn(acc[0], acc[1]);
        __half2 h1 = __floats2half2_rn(acc[2], acc[3]);
        __half2 h2 = __floats2half2_rn(acc[4], acc[5]);
        __half2 h3 = __floats2half2_rn(acc[6], acc[7]);
        uint4 r;
        r.x = *(const unsigned*)&h0; r.y = *(const unsigned*)&h1;
        r.z = *(const unsigned*)&h2; r.w = *(const unsigned*)&h3;
        ((uint4*)outp)[(size_t)node * NT + c] = r;
    } else {
        float* o = (float*)outp + (size_t)node * F + c * 8;
        *(float4*)(o + 0) = make_float4(acc[0], acc[1], acc[2], acc[3]);
        *(float4*)(o + 4) = make_float4(acc[4], acc[5], acc[6], acc[7]);
    }
}

// ---- tensor-core GEMM: D[M,N] = A[M,K] @ W[K,N], fp16 in / fp32 acc --------

template <int K, int N>
__global__ void mma_gemm_k(const __half* __restrict__ A,
                           const __half* __restrict__ Wt,
                           __half* __restrict__ D) {
    constexpr int WN = (N >= 64) ? 64 : N;       // warp n-extent
    constexpr int TN = WN / 8;                   // n8 tiles per warp
    constexpr int WARPS_N = N / WN;
    constexpr int WARPS_M = 8 / WARPS_N;
    constexpr int BM = WARPS_M * 16;
    constexpr int PITCH = K + 8;                 // +16B pad -> bank rotation
    constexpr int KC = K / 16;                   // k16 chunks

    __shared__ __half sA[BM * PITCH];

    const int tid = threadIdx.x;
    const int lane = tid & 31;
    const int wid = tid >> 5;
    const int wm = wid % WARPS_M;
    const int wn = wid / WARPS_M;
    const int blockStart = blockIdx.x * BM;

    for (int i = tid; i < BM * (K / 8); i += 256) {
        int row = i / (K / 8), chunk = i % (K / 8);
        int node = blockStart + row;
        uint4 v = make_uint4(0, 0, 0, 0);
        if (node < NN) v = ((const uint4*)A)[(size_t)node * (K / 8) + chunk];
        *(uint4*)(&sA[row * PITCH + chunk * 8]) = v;
    }
    __syncthreads();

    float acc[TN][4];
#pragma unroll
    for (int t = 0; t < TN; t++)
#pragma unroll
        for (int i = 0; i < 4; i++) acc[t][i] = 0.f;

    const int q = lane >> 3, r = lane & 7;
    const int arow = wm * 16 + r + 8 * (q & 1);
    const int acol0 = 8 * (q >> 1);
    unsigned abase;
    {
        const void* p = &sA[arow * PITCH + acol0];
        asm("{ .reg .u64 t; cvta.to.shared.u64 t, %1; cvt.u32.u64 %0, t; }"
            : "=r"(abase) : "l"(p));
    }

    const __half* wbase = Wt + (size_t)(wn * WN + (lane >> 2)) * K + (lane & 3) * 2;

#pragma unroll
    for (int kc = 0; kc < KC; kc++) {
        unsigned a0, a1, a2, a3;
        asm volatile("ldmatrix.sync.aligned.m8n8.x4.shared.b16 {%0,%1,%2,%3}, [%4];"
                     : "=r"(a0), "=r"(a1), "=r"(a2), "=r"(a3)
                     : "r"(abase + kc * 32));
#pragma unroll
        for (int tn = 0; tn < TN; tn++) {
            unsigned b0 = *(const unsigned*)(wbase + (size_t)tn * 8 * K + kc * 16);
            unsigned b1 = *(const unsigned*)(wbase + (size_t)tn * 8 * K + kc * 16 + 8);
            asm volatile(
                "mma.sync.aligned.m16n8k16.row.col.f32.f16.f16.f32 "
                "{%0,%1,%2,%3}, {%4,%5,%6,%7}, {%8,%9}, {%0,%1,%2,%3};"
                : "+f"(acc[tn][0]), "+f"(acc[tn][1]), "+f"(acc[tn][2]), "+f"(acc[tn][3])
                : "r"(a0), "r"(a1), "r"(a2), "r"(a3), "r"(b0), "r"(b1));
        }
    }

    const int node0 = blockStart + wm * 16 + (lane >> 2);
    const int node1 = node0 + 8;
#pragma unroll
    for (int tn = 0; tn < TN; tn++) {
        int gcol = wn * WN + tn * 8 + (lane & 3) * 2;
        if (node0 < NN) {
            __half2 h = __floats2half2_rn(acc[tn][0], acc[tn][1]);
            *(unsigned*)(D + (size_t)node0 * N + gcol) = *(const unsigned*)&h;
        }
        if (node1 < NN) {
            __half2 h = __floats2half2_rn(acc[tn][2], acc[tn][3]);
            *(unsigned*)(D + (size_t)node1 * N + gcol) = *(const unsigned*)&h;
        }
    }
}

// ---- fused gc1: gather 16-wide scaled x + (agg @ W1)*in_norm+b1, relu ------

__global__ void g1_k(const float* __restrict__ x, const float* __restrict__ W1,
                     const float* __restrict__ b1, __half* __restrict__ out) {
    __shared__ float sX[64 * 16];
    const int tid = threadIdx.x;
    const int nbase = blockIdx.x * 64;

    {
        int g = tid / 4, c = tid % 4;
        int node = nbase + g;
        float4 a = make_float4(0.f, 0.f, 0.f, 0.f);
        if (node < NN) {
            int beg = g_off[node], end = g_off[node + 1];
            for (int e = beg; e < end; e++) {
                int s = g_edge[e].x;
                float w = g_norm_out[s];
                float4 v = *(const float4*)(x + (size_t)s * 16 + c * 4);
                a.x += v.x * w; a.y += v.y * w; a.z += v.z * w; a.w += v.w * w;
            }
        }
        *(float4*)(&sX[g * 16 + c * 4]) = a;
    }
    __syncthreads();

    const int j = tid;
    float w[16];
#pragma unroll
    for (int k = 0; k < 16; k++) w[k] = W1[k * 256 + j];
    float bj = b1[j];
#pragma unroll 4
    for (int ln = 0; ln < 64; ln++) {
        int node = nbase + ln;
        if (node >= NN) break;
        float acc = 0.f;
#pragma unroll
        for (int k = 0; k < 16; k++) acc += sX[ln * 16 + k] * w[k];
        acc = acc * g_norm_in[node] + bj;
        out[(size_t)node * 256 + j] = __float2half(fmaxf(acc, 0.f));
    }
}

// ---- fused gc4-agg + gemm5: h4 = relu(agg(m4)*ni+b4); m5 = (h4*no)@W5 ------

__global__ void g45_k(const __half* __restrict__ m4, const float* __restrict__ b4,
                      const float* __restrict__ W5, float* __restrict__ m5) {
    __shared__ float sH[64 * 32];
    __shared__ float sW[32 * 4];
    const int tid = threadIdx.x;
    if (tid < 128) sW[tid] = W5[tid];
    const int g = tid / 4, c = tid % 4;     // 64 nodes x 4 threads
    const int node = blockIdx.x * 64 + g;

    float acc[8];
#pragma unroll
    for (int i = 0; i < 8; i++) acc[i] = 0.f;
    if (node < NN) {
        int beg = g_off[node], end = g_off[node + 1];
        const uint4* base = (const uint4*)m4;     // row stride = 4 uint4s
        int e = beg;
        for (; e + 2 <= end; e += 2) {
            int2 sc0 = g_edge[e], sc1 = g_edge[e + 1];
            uint4 r0 = base[(size_t)sc0.x * 4 + c];
            uint4 r1 = base[(size_t)sc1.x * 4 + c];
            acc8(acc, r0, 1.f);
            acc8(acc, r1, 1.f);
        }
        if (e < end) {
            int2 sc = g_edge[e];
            uint4 r = base[(size_t)sc.x * 4 + c];
            acc8(acc, r, 1.f);
        }
        float ni = g_norm_in[node];
        float no = g_norm_out[node];
#pragma unroll
        for (int i = 0; i < 8; i++)
            acc[i] = fmaxf(acc[i] * ni + b4[c * 8 + i], 0.f) * no;
    }
#pragma unroll
    for (int i = 0; i < 8; i++) sH[g * 32 + c * 8 + i] = acc[i];
    __syncthreads();

    if (node >= NN) return;
    float o = 0.f;
#pragma unroll
    for (int k = 0; k < 32; k++) o += sH[g * 32 + k] * sW[k * 4 + c];
    m5[(size_t)node * 4 + c] = o;
}

// ---------------------------------------------------------------------------

static inline int cdiv(long long a, int b) { return (int)((a + b - 1) / b); }

extern "C" void kernel_launch(void* const* d_in, const int* in_sizes, int n_in,
                              void* d_out, int out_size) {
    (void)in_sizes; (void)n_in; (void)out_size;
    const float* x    = (const float*)d_in[0];
    const float* efet = (const float*)d_in[1];
    const int*   src  = (const int*)d_in[2];
    const int*   dst  = (const int*)d_in[3];
    const float* W1 = (const float*)d_in[4];  const float* b1 = (const float*)d_in[5];
    const float* W2 = (const float*)d_in[6];  const float* b2 = (const float*)d_in[7];
    const float* W3 = (const float*)d_in[8];  const float* b3 = (const float*)d_in[9];
    const float* W4 = (const float*)d_in[10]; const float* b4 = (const float*)d_in[11];
    const float* W5 = (const float*)d_in[12]; const float* b5 = (const float*)d_in[13];
    float* out = (float*)d_out;

    float *bufA, *bufB, *bufC;
    int *cnt3;
    __half *w2t, *w3t, *w4t;
    cudaGetSymbolAddress((void**)&bufA, g_bufA);
    cudaGetSymbolAddress((void**)&bufB, g_bufB);
    cudaGetSymbolAddress((void**)&bufC, g_bufC);
    cudaGetSymbolAddress((void**)&cnt3, g_cnt3);
    cudaGetSymbolAddress((void**)&w2t, g_w2t);
    cudaGetSymbolAddress((void**)&w3t, g_w3t);
    cudaGetSymbolAddress((void**)&w4t, g_w4t);
    __half* hA = (__half*)bufA;
    __half* hB = (__half*)bufB;
    __half* hC = (__half*)bufC;

    const int TB = 256;

    // ---- preprocessing (R15 form)
    cudaMemsetAsync(cnt3, 0, 3 * NN * sizeof(int));
    deg_k<<<cdiv(NE, TB), TB>>>(src, dst);
    bscan_k<<<NB_SCAN, 256>>>();
    badd_k<<<NB_SCAN, 256>>>();
    fill_k<<<cdiv(NE, TB), TB>>>(src, dst, efet);
    wcvt_all_k<<<cdiv(256 * 128 + 128 * 64 + 64 * 32, TB), TB>>>(W2, W3, W4);

    // ---- gc1 fused: g1 = relu((agg16(x*no) @ W1)*ni + b1) -> fp16
    g1_k<<<cdiv(NN, 64), TB>>>(x, W1, b1, hB);                                // g1: hB

    // ---- y1 = g1 @ W2 (mma 256->128) BEFORE ewa1 (commuted)
    mma_gemm_k<256, 128><<<cdiv(NN, 64), TB>>>(hB, w2t, hA);                  // y1: hA
    // ---- ewa1 at width 128: m2 = ewa(y1) * out_norm (relu is identity)
    gather_h_k<128, 1, false, false, true, true><<<cdiv(NN, 16), TB>>>(hA, nullptr, hC);
    // ---- gc2 aggregation: g2 = relu(agg(m2)*ni + b2)
    gather_h_k<128, 0, true, true, false, true><<<cdiv(NN, 16), TB>>>(hC, b2, hB); // g2: hB

    // ---- y2 = g2 @ W3 (mma 128->64) BEFORE ewa2
    mma_gemm_k<128, 64><<<cdiv(NN, 128), TB>>>(hB, w3t, hA);                  // y2: hA
    // ---- ewa2 at width 64
    gather_h_k<64, 1, false, false, true, true><<<cdiv(NN, 32), TB>>>(hA, nullptr, hC);
    // ---- gc3 aggregation: g3 = relu(agg(m3)*ni + b3)
    gather_h_k<64, 0, true, true, false, true><<<cdiv(NN, 32), TB>>>(hC, b3, hB);  // g3: hB

    // ---- y3 = g3 @ W4 (mma 64->32) BEFORE ewa3
    mma_gemm_k<64, 32><<<cdiv(NN, 128), TB>>>(hB, w4t, hA);                   // y3: hA
    // ---- ewa3 at width 32
    gather_h_k<32, 1, false, false, true, true><<<cdiv(NN, 64), TB>>>(hA, nullptr, hC);

    // ---- gc4-agg + gemm5 fused: m5 = (relu(agg(m4)*ni+b4)*no) @ W5
    g45_k<<<cdiv(NN, 64), TB>>>(hC, b4, W5, bufB);                            // m5: bufB

    // ---- gc5 aggregation: out = agg(m5)*ni + b5
    gather_k<4, 0, true, false><<<cdiv(NN, 256), TB>>>(bufB, b5, out);
}